// round 8
// baseline (speedup 1.0000x reference)
#include <cuda_runtime.h>
#include <cuda_fp16.h>
#include <cstdint>

// FP4(E2M1) weight-only linear: hybrid tensor(fp16 mma.sync) + fp32 FFMA2.
// out[32,8192] = inp[32,8192] @ W^T + bias,  W[n,k]=LUT(nib)*scales[n,k/16]*amax
// Per CTA k-column (1024): first 800 k on tensor pipe (exact fp16 LUT x fp16
// activations, scale folded per A-register), last 224 k on FMA pipe in exact
// fp32 (SMEM-staged). Warp-phase staggering keeps both pipes busy.

#define TOKENS   32
#define NFEAT    8192
#define KFEAT    8192
#define NWIN     (KFEAT / 16)
#define NMP      (NWIN / 2)            // 256
#define KSPLIT   8
#define MMA_MP   25                    // 800 k on tensor
#define FF_K     224                   // 224 k on fma
#define FF_BLKS  (FF_K / 16)           // 14

__device__ uint4 g_bfrag[NMP * 4 * 32];             // fp16x2 x4 per [mp][g][lane] (2 MB)
__device__ float g_part[KSPLIT * TOKENS * NFEAT];   // split-K partials (8 MB)

// ---------- decode helpers ----------
__device__ __forceinline__ uint32_t dec16(uint32_t b){   // byte -> fp16x2 LUT pair
    uint32_t h = __byte_perm(0x3E3C3800u, 0x46444240u, b & 0x77u);
    uint32_t r = __byte_perm(h, 0u, 0x1404u);
    return r | ((b & 0x8u) << 12) | ((b & 0x80u) << 24);
}
// byte -> two exact fp32 LUT values (bit-built)
__device__ __forceinline__ void dec32(uint32_t b, float &w0, float &w1){
    uint32_t bs = b & 0x77u;
    uint32_t rA = __byte_perm(0x3F3F3F00u, 0x40404040u, bs);
    uint32_t rB = __byte_perm(0xC0800000u, 0xC0804000u, bs);
    uint32_t comb = __byte_perm(rA, rB, 0x1504u);
    w0 = __uint_as_float((comb << 16)         | ((b & 0x8u)  << 28));
    w1 = __uint_as_float((comb & 0xFFFF0000u) | ((b & 0x80u) << 24));
}
__device__ __forceinline__ uint32_t hmul2(uint32_t a, uint32_t b){
    uint32_t r; asm("mul.rn.f16x2 %0, %1, %2;" : "=r"(r) : "r"(a), "r"(b)); return r;
}
__device__ __forceinline__ uint32_t dup_f16(float s){
    uint32_t r; asm("cvt.rn.f16x2.f32 %0, %1, %1;" : "=r"(r) : "f"(s)); return r;
}
__device__ __forceinline__ uint32_t pack_f16x2(float lo, float hi){
    uint32_t r; asm("cvt.rn.f16x2.f32 %0, %1, %2;" : "=r"(r) : "f"(hi), "f"(lo)); return r;
}
__device__ __forceinline__ unsigned long long dup2(float w){
    unsigned long long r; asm("mov.b64 %0, {%1, %1};" : "=l"(r) : "f"(w)); return r;
}
__device__ __forceinline__ void fma2(unsigned long long &acc, unsigned long long a, unsigned long long b){
    asm("fma.rn.f32x2 %0, %1, %2, %0;" : "+l"(acc) : "l"(a), "l"(b));
}
__device__ __forceinline__ void unpack2(unsigned long long v, float &lo, float &hi){
    asm("mov.b64 {%0, %1}, %2;" : "=f"(lo), "=f"(hi) : "l"(v));
}
__device__ __forceinline__ void mma_acc(
    float& d0, float& d1, float& d2, float& d3,
    uint32_t a0, uint32_t a1, uint32_t a2, uint32_t a3,
    uint32_t b0, uint32_t b1)
{
    asm("mma.sync.aligned.m16n8k16.row.col.f32.f16.f16.f32 "
        "{%0,%1,%2,%3}, {%4,%5,%6,%7}, {%8,%9}, {%0,%1,%2,%3};"
        : "+f"(d0), "+f"(d1), "+f"(d2), "+f"(d3)
        : "r"(a0), "r"(a1), "r"(a2), "r"(a3), "r"(b0), "r"(b1));
}

// ---------------- prologue: fp16 B fragments (2x parallel) ----------------
__global__ void bfrag_kernel(const float* __restrict__ inp, const float* __restrict__ amax){
    int t = blockIdx.x * blockDim.x + threadIdx.x;   // 0..65535 (uint2 halves)
    int e = t >> 1, h = t & 1;
    int lane = e & 31, g = (e >> 5) & 3, mp = e >> 7;
    int c = lane & 3, n = g * 8 + (lane >> 2);
    int k0 = 32 * mp + 8 * c + 4 * h;
    const float am = __ldg(amax);
    float4 a = *reinterpret_cast<const float4*>(inp + (size_t)n * KFEAT + k0);
    reinterpret_cast<uint2*>(g_bfrag)[t] =
        make_uint2(pack_f16x2(a.x * am, a.y * am), pack_f16x2(a.z * am, a.w * am));
}

// ---------------- hybrid main kernel ----------------
// grid (64, 8), 128 thr. Warp = 32 rows x 32 tokens.
__global__ void __launch_bounds__(128, 4) fp4_hybrid_kernel(
    const int*   __restrict__ qw,
    const float* __restrict__ scales,
    const float* __restrict__ inp,
    const float* __restrict__ amax)
{
    __shared__ float    aS[FF_K * 32];        // activations [k][m] (28672 B)
    __shared__ uint32_t qS[128 * 32];         // packed qweight bytes, swizzled (16384 B)

    const int tid = threadIdx.x, wid = tid >> 5, lane = tid & 31;
    const int c  = lane & 3, rl = lane >> 2;
    const int r0 = blockIdx.x * 128 + wid * 32 + rl;
    const int mpb = blockIdx.y * 32;                 // global mp base of this column
    const float am = __ldg(amax);

    // ---- stage FFMA-range activations: aS[k][m] = inp[m][kab + k] ----
    const int kab = blockIdx.y * 1024 + MMA_MP * 32;
    #pragma unroll
    for (int i = 0; i < 14; ++i){
        int e4 = tid + 128 * i;                      // 0..1791 (32 rows x 56 float4)
        int m  = e4 / 56, kq = e4 - m * 56;
        const float4 v = *reinterpret_cast<const float4*>(inp + (size_t)m * KFEAT + kab + 4 * kq);
        aS[(4 * kq + 0) * 32 + m] = v.x;
        aS[(4 * kq + 1) * 32 + m] = v.y;
        aS[(4 * kq + 2) * 32 + m] = v.z;
        aS[(4 * kq + 3) * 32 + m] = v.w;
    }
    // ---- stage FFMA-range qweight payload bytes (packed 4/uint, bank-swizzled) ----
    {
        const int qbase = blockIdx.y * 512 + MMA_MP * 16;   // int offset within row
        const int nb0 = blockIdx.x * 128;
        #pragma unroll
        for (int i = 0; i < 28; ++i){
            int u = tid + 128 * i;                   // 0..3583 (128 rows x 28 uints)
            int row = u / 28, cu = u - row * 28;
            const uint4 q = *reinterpret_cast<const uint4*>(
                qw + (size_t)(nb0 + row) * (KFEAT / 2) + qbase + 4 * cu);
            uint32_t t1 = __byte_perm(q.x, q.y, 0x0040u);
            uint32_t t2 = __byte_perm(q.z, q.w, 0x0040u);
            qS[row * 32 + ((cu + row) & 31)] = __byte_perm(t1, t2, 0x5410u);
        }
    }
    __syncthreads();

    float acc[4][8];
    #pragma unroll
    for (int g = 0; g < 4; ++g)
        #pragma unroll
        for (int j = 0; j < 8; ++j) acc[g][j] = 0.f;

    const uint4* qr0 = reinterpret_cast<const uint4*>(qw + (size_t)(r0     ) * (KFEAT / 2)) + c;
    const uint4* qr1 = reinterpret_cast<const uint4*>(qw + (size_t)(r0 +  8) * (KFEAT / 2)) + c;
    const uint4* qr2 = reinterpret_cast<const uint4*>(qw + (size_t)(r0 + 16) * (KFEAT / 2)) + c;
    const uint4* qr3 = reinterpret_cast<const uint4*>(qw + (size_t)(r0 + 24) * (KFEAT / 2)) + c;
    const float2* sr0 = reinterpret_cast<const float2*>(scales + (size_t)(r0     ) * NWIN);
    const float2* sr1 = reinterpret_cast<const float2*>(scales + (size_t)(r0 +  8) * NWIN);
    const float2* sr2 = reinterpret_cast<const float2*>(scales + (size_t)(r0 + 16) * NWIN);
    const float2* sr3 = reinterpret_cast<const float2*>(scales + (size_t)(r0 + 24) * NWIN);
    const bool hiblk = (lane & 2) != 0;
    const bool mma_first = (wid < 2);

    #pragma unroll 1
    for (int phase = 0; phase < 2; ++phase){
        if ((phase == 0) == mma_first){
            // ================= MMA section: 25 mps =================
            #pragma unroll 5
            for (int mpl = 0; mpl < MMA_MP; ++mpl){
                const int mp = mpb + mpl;
                const uint4 q0 = __ldg(qr0 + mp * 4);
                const uint4 q1 = __ldg(qr1 + mp * 4);
                const uint4 q2 = __ldg(qr2 + mp * 4);
                const uint4 q3 = __ldg(qr3 + mp * 4);
                const float2 t0 = __ldg(sr0 + mp);
                const float2 t1 = __ldg(sr1 + mp);
                const float2 t2 = __ldg(sr2 + mp);
                const float2 t3 = __ldg(sr3 + mp);
                const uint32_t h0 = dup_f16(hiblk ? t0.y : t0.x);
                const uint32_t h1 = dup_f16(hiblk ? t1.y : t1.x);
                const uint32_t h2 = dup_f16(hiblk ? t2.y : t2.x);
                const uint32_t h3 = dup_f16(hiblk ? t3.y : t3.x);
                uint4 bf[4];
                #pragma unroll
                for (int g = 0; g < 4; ++g)
                    bf[g] = __ldg(&g_bfrag[(size_t)(mp * 4 + g) * 32 + lane]);
                {   // e = 0
                    const uint32_t a00 = hmul2(dec16(q0.x), h0), a02 = hmul2(dec16(q0.y), h0);
                    const uint32_t a01 = hmul2(dec16(q1.x), h1), a03 = hmul2(dec16(q1.y), h1);
                    const uint32_t a10 = hmul2(dec16(q2.x), h2), a12 = hmul2(dec16(q2.y), h2);
                    const uint32_t a11 = hmul2(dec16(q3.x), h3), a13 = hmul2(dec16(q3.y), h3);
                    #pragma unroll
                    for (int g = 0; g < 4; ++g){
                        mma_acc(acc[g][0], acc[g][1], acc[g][2], acc[g][3],
                                a00, a01, a02, a03, bf[g].x, bf[g].y);
                        mma_acc(acc[g][4], acc[g][5], acc[g][6], acc[g][7],
                                a10, a11, a12, a13, bf[g].x, bf[g].y);
                    }
                }
                {   // e = 1
                    const uint32_t a00 = hmul2(dec16(q0.z), h0), a02 = hmul2(dec16(q0.w), h0);
                    const uint32_t a01 = hmul2(dec16(q1.z), h1), a03 = hmul2(dec16(q1.w), h1);
                    const uint32_t a10 = hmul2(dec16(q2.z), h2), a12 = hmul2(dec16(q2.w), h2);
                    const uint32_t a11 = hmul2(dec16(q3.z), h3), a13 = hmul2(dec16(q3.w), h3);
                    #pragma unroll
                    for (int g = 0; g < 4; ++g){
                        mma_acc(acc[g][0], acc[g][1], acc[g][2], acc[g][3],
                                a00, a01, a02, a03, bf[g].z, bf[g].w);
                        mma_acc(acc[g][4], acc[g][5], acc[g][6], acc[g][7],
                                a10, a11, a12, a13, bf[g].z, bf[g].w);
                    }
                }
            }
        } else {
            // ================= FFMA section: 224 k, exact fp32 =================
            const int sblk = blockIdx.y * 64 + MMA_MP * 2;   // scale block base
            #pragma unroll 1
            for (int b = 0; b < FF_BLKS; ++b){
                float sj[4];
                #pragma unroll
                for (int j = 0; j < 4; ++j)
                    sj[j] = __ldg(scales + (size_t)(r0 + 8 * j) * NWIN + sblk + b) * am;

                uint32_t qv[4][2];
                #pragma unroll
                for (int j = 0; j < 4; ++j){
                    const int row = wid * 32 + rl + 8 * j;
                    qv[j][0] = qS[row * 32 + ((2 * b     + row) & 31)];
                    qv[j][1] = qS[row * 32 + ((2 * b + 1 + row) & 31)];
                }

                unsigned long long ptmp[4][4];
                #pragma unroll
                for (int j = 0; j < 4; ++j)
                    #pragma unroll
                    for (int g = 0; g < 4; ++g) ptmp[j][g] = 0ull;

                #pragma unroll
                for (int h = 0; h < 2; ++h){
                    #pragma unroll
                    for (int p = 0; p < 4; ++p){
                        const int k = 16 * b + 8 * h + 2 * p;
                        unsigned long long ae[4], ao[4];
                        #pragma unroll
                        for (int g = 0; g < 4; ++g){
                            ae[g] = *reinterpret_cast<const unsigned long long*>(aS + (k    ) * 32 + 8 * g + 2 * c);
                            ao[g] = *reinterpret_cast<const unsigned long long*>(aS + (k + 1) * 32 + 8 * g + 2 * c);
                        }
                        #pragma unroll
                        for (int j = 0; j < 4; ++j){
                            const uint32_t byte = __byte_perm(qv[j][h], 0u, 0x4440u | p);
                            float w0, w1;
                            dec32(byte, w0, w1);
                            const unsigned long long d0 = dup2(w0), d1 = dup2(w1);
                            #pragma unroll
                            for (int g = 0; g < 4; ++g){
                                fma2(ptmp[j][g], ae[g], d0);
                                fma2(ptmp[j][g], ao[g], d1);
                            }
                        }
                    }
                }
                // merge with per-row fp32 scale
                #pragma unroll
                for (int j = 0; j < 4; ++j)
                    #pragma unroll
                    for (int g = 0; g < 4; ++g){
                        float lo, hi;
                        unpack2(ptmp[j][g], lo, hi);
                        acc[g][2 * j    ] = fmaf(sj[j], lo, acc[g][2 * j    ]);
                        acc[g][2 * j + 1] = fmaf(sj[j], hi, acc[g][2 * j + 1]);
                    }
            }
        }
    }

    // epilogue
    float* base = g_part + (size_t)blockIdx.y * (TOKENS * NFEAT);
    #pragma unroll
    for (int g = 0; g < 4; ++g){
        const int t0c = g * 8 + 2 * c;
        base[(size_t)t0c       * NFEAT + r0     ] = acc[g][0];
        base[(size_t)(t0c + 1) * NFEAT + r0     ] = acc[g][1];
        base[(size_t)t0c       * NFEAT + r0 +  8] = acc[g][2];
        base[(size_t)(t0c + 1) * NFEAT + r0 +  8] = acc[g][3];
        base[(size_t)t0c       * NFEAT + r0 + 16] = acc[g][4];
        base[(size_t)(t0c + 1) * NFEAT + r0 + 16] = acc[g][5];
        base[(size_t)t0c       * NFEAT + r0 + 24] = acc[g][6];
        base[(size_t)(t0c + 1) * NFEAT + r0 + 24] = acc[g][7];
    }
}

// ---------------- reduce split-K + bias ----------------
__global__ void reduce_kernel(const float* __restrict__ bias, float* __restrict__ out){
    int i4 = blockIdx.x * blockDim.x + threadIdx.x;
    if (i4 >= (TOKENS * NFEAT) / 4) return;
    const float4 b = *reinterpret_cast<const float4*>(bias + ((i4 * 4) & (NFEAT - 1)));
    float4 s = b;
    #pragma unroll
    for (int cp = 0; cp < KSPLIT; ++cp){
        const float4 v = *reinterpret_cast<const float4*>(g_part + (size_t)cp * (TOKENS * NFEAT) + i4 * 4);
        s.x += v.x; s.y += v.y; s.z += v.z; s.w += v.w;
    }
    reinterpret_cast<float4*>(out)[i4] = s;
}

extern "C" void kernel_launch(void* const* d_in, const int* in_sizes, int n_in,
                              void* d_out, int out_size)
{
    const float* inp    = (const float*)d_in[0];
    const int*   qw     = (const int*)  d_in[1];
    const float* scales = (const float*)d_in[2];
    const float* amax   = (const float*)d_in[3];
    const float* bias   = (const float*)d_in[4];
    float* out = (float*)d_out;

    bfrag_kernel<<<256, 256>>>(inp, amax);

    dim3 grid(NFEAT / 128, KSPLIT);
    fp4_hybrid_kernel<<<grid, 128>>>(qw, scales, inp, amax);

    reduce_kernel<<<(TOKENS * NFEAT / 4 + 255) / 256, 256>>>(bias, out);
}

// round 9
// speedup vs baseline: 2.0836x; 2.0836x over previous
#include <cuda_runtime.h>
#include <cuda_fp16.h>
#include <cstdint>

// FP4(E2M1) weight-only linear, single fused persistent kernel:
//   phase 0: build fp16 activation fragments (amax folded)
//   phase 1: fp16 mma.sync GEMM, scales folded into fp16 A registers (R6 loop)
//   phase 2: split-K reduce + bias
// Global sense-reversing barriers between phases (512 CTAs = 1 wave, occ 4).
// out[32,8192] = inp[32,8192] @ W^T + bias, W[n,k]=LUT(nib)*scales[n,k/16]*amax

#define TOKENS   32
#define NFEAT    8192
#define KFEAT    8192
#define NWIN     (KFEAT / 16)          // 512 mma k-steps
#define NMP      (NWIN / 2)            // 256 window-pairs
#define KSPLIT   8
#define MP_PER_CTA  (NMP / KSPLIT)     // 32
#define NCTAS    512

__device__ uint4 g_bfrag[NMP * 4 * 32];             // fp16x2 x4 per [mp][g][lane] (2 MB)
__device__ float g_part[KSPLIT * TOKENS * NFEAT];   // split-K partials (8 MB)
__device__ unsigned g_cnt[2];                        // barrier arrive counters (zero-init)
__device__ volatile unsigned g_phase[2];             // barrier phase flags

// ---------- helpers ----------
__device__ __forceinline__ uint32_t dec16(uint32_t b){   // byte -> fp16x2 LUT pair (exact)
    uint32_t h = __byte_perm(0x3E3C3800u, 0x46444240u, b & 0x77u);
    uint32_t r = __byte_perm(h, 0u, 0x1404u);
    return r | ((b & 0x8u) << 12) | ((b & 0x80u) << 24);
}
__device__ __forceinline__ uint32_t hmul2(uint32_t a, uint32_t b){
    uint32_t r; asm("mul.rn.f16x2 %0, %1, %2;" : "=r"(r) : "r"(a), "r"(b)); return r;
}
__device__ __forceinline__ uint32_t dup_f16(float s){
    uint32_t r; asm("cvt.rn.f16x2.f32 %0, %1, %1;" : "=r"(r) : "f"(s)); return r;
}
__device__ __forceinline__ uint32_t pack_f16x2(float lo, float hi){
    uint32_t r; asm("cvt.rn.f16x2.f32 %0, %1, %2;" : "=r"(r) : "f"(hi), "f"(lo)); return r;
}
__device__ __forceinline__ void mma_acc(
    float& d0, float& d1, float& d2, float& d3,
    uint32_t a0, uint32_t a1, uint32_t a2, uint32_t a3,
    uint32_t b0, uint32_t b1)
{
    asm("mma.sync.aligned.m16n8k16.row.col.f32.f16.f16.f32 "
        "{%0,%1,%2,%3}, {%4,%5,%6,%7}, {%8,%9}, {%0,%1,%2,%3};"
        : "+f"(d0), "+f"(d1), "+f"(d2), "+f"(d3)
        : "r"(a0), "r"(a1), "r"(a2), "r"(a3), "r"(b0), "r"(b1));
}

// sense-reversing grid barrier; replay-safe (counter self-resets, phase toggles)
__device__ __forceinline__ void grid_barrier(int b){
    __syncthreads();
    if (threadIdx.x == 0){
        __threadfence();
        unsigned p = g_phase[b];
        unsigned arrived = atomicAdd(&g_cnt[b], 1u) + 1u;
        if (arrived == NCTAS){
            g_cnt[b] = 0u;
            __threadfence();
            g_phase[b] = p + 1u;
        } else {
            while (g_phase[b] == p) { __nanosleep(32); }
        }
    }
    __syncthreads();
    __threadfence();
}

// ---------------- fused persistent kernel ----------------
// grid (64, 8), 128 thr, occ 4 -> 512 CTAs = one wave (<= 592 slots).
__global__ void __launch_bounds__(128, 4) fp4_fused_kernel(
    const int*   __restrict__ qw,       // [N, K/2] one packed byte per int32
    const float* __restrict__ scales,   // [N, K/16]
    const float* __restrict__ inp,      // [M, K]
    const float* __restrict__ amax,     // [1]
    const float* __restrict__ bias,     // [N]
    float*       __restrict__ out)      // [M, N]
{
    const int tid = threadIdx.x, wid = tid >> 5, lane = tid & 31;
    const int bid = blockIdx.y * 64 + blockIdx.x;
    const int t   = bid * 128 + tid;                  // flat 0..65535

    // ========== phase 0: build fp16 B fragments (one uint2 per thread) ==========
    {
        int e = t >> 1, h = t & 1;
        int bl = e & 31, g = (e >> 5) & 3, mp = e >> 7;
        int bc = bl & 3, n = g * 8 + (bl >> 2);
        int k0 = 32 * mp + 8 * bc + 4 * h;
        const float am = __ldg(amax);
        float4 a = *reinterpret_cast<const float4*>(inp + (size_t)n * KFEAT + k0);
        reinterpret_cast<uint2*>(g_bfrag)[t] =
            make_uint2(pack_f16x2(a.x * am, a.y * am), pack_f16x2(a.z * am, a.w * am));
    }
    grid_barrier(0);

    // ========== phase 1: GEMM (R6 loop, unchanged) ==========
    {
        const int c  = lane & 3;
        const int r0 = blockIdx.x * 128 + wid * 32 + (lane >> 2);   // rows r0,+8,+16,+24
        const int mpb = blockIdx.y * MP_PER_CTA;

        float acc[4][8];
        #pragma unroll
        for (int g = 0; g < 4; ++g)
            #pragma unroll
            for (int j = 0; j < 8; ++j) acc[g][j] = 0.f;

        const uint4* qr0 = reinterpret_cast<const uint4*>(qw + (size_t)(r0     ) * (KFEAT / 2)) + c;
        const uint4* qr1 = reinterpret_cast<const uint4*>(qw + (size_t)(r0 +  8) * (KFEAT / 2)) + c;
        const uint4* qr2 = reinterpret_cast<const uint4*>(qw + (size_t)(r0 + 16) * (KFEAT / 2)) + c;
        const uint4* qr3 = reinterpret_cast<const uint4*>(qw + (size_t)(r0 + 24) * (KFEAT / 2)) + c;
        const float2* sr0 = reinterpret_cast<const float2*>(scales + (size_t)(r0     ) * NWIN);
        const float2* sr1 = reinterpret_cast<const float2*>(scales + (size_t)(r0 +  8) * NWIN);
        const float2* sr2 = reinterpret_cast<const float2*>(scales + (size_t)(r0 + 16) * NWIN);
        const float2* sr3 = reinterpret_cast<const float2*>(scales + (size_t)(r0 + 24) * NWIN);
        const bool hiblk = (lane & 2) != 0;

        #pragma unroll 4
        for (int mpl = 0; mpl < MP_PER_CTA; ++mpl){
            const int mp = mpb + mpl;

            const uint4 q0 = __ldg(qr0 + mp * 4);
            const uint4 q1 = __ldg(qr1 + mp * 4);
            const uint4 q2 = __ldg(qr2 + mp * 4);
            const uint4 q3 = __ldg(qr3 + mp * 4);

            const float2 t0 = __ldg(sr0 + mp);
            const float2 t1 = __ldg(sr1 + mp);
            const float2 t2 = __ldg(sr2 + mp);
            const float2 t3 = __ldg(sr3 + mp);
            const uint32_t h0 = dup_f16(hiblk ? t0.y : t0.x);
            const uint32_t h1 = dup_f16(hiblk ? t1.y : t1.x);
            const uint32_t h2 = dup_f16(hiblk ? t2.y : t2.x);
            const uint32_t h3 = dup_f16(hiblk ? t3.y : t3.x);

            uint4 bf[4];
            #pragma unroll
            for (int g = 0; g < 4; ++g)
                bf[g] = __ldg(&g_bfrag[(size_t)(mp * 4 + g) * 32 + lane]);

            {   // e = 0 (k 0..15 of pair)
                const uint32_t a00 = hmul2(dec16(q0.x), h0), a02 = hmul2(dec16(q0.y), h0);
                const uint32_t a01 = hmul2(dec16(q1.x), h1), a03 = hmul2(dec16(q1.y), h1);
                const uint32_t a10 = hmul2(dec16(q2.x), h2), a12 = hmul2(dec16(q2.y), h2);
                const uint32_t a11 = hmul2(dec16(q3.x), h3), a13 = hmul2(dec16(q3.y), h3);
                #pragma unroll
                for (int g = 0; g < 4; ++g){
                    mma_acc(acc[g][0], acc[g][1], acc[g][2], acc[g][3],
                            a00, a01, a02, a03, bf[g].x, bf[g].y);
                    mma_acc(acc[g][4], acc[g][5], acc[g][6], acc[g][7],
                            a10, a11, a12, a13, bf[g].x, bf[g].y);
                }
            }
            {   // e = 1 (k 16..31 of pair)
                const uint32_t a00 = hmul2(dec16(q0.z), h0), a02 = hmul2(dec16(q0.w), h0);
                const uint32_t a01 = hmul2(dec16(q1.z), h1), a03 = hmul2(dec16(q1.w), h1);
                const uint32_t a10 = hmul2(dec16(q2.z), h2), a12 = hmul2(dec16(q2.w), h2);
                const uint32_t a11 = hmul2(dec16(q3.z), h3), a13 = hmul2(dec16(q3.w), h3);
                #pragma unroll
                for (int g = 0; g < 4; ++g){
                    mma_acc(acc[g][0], acc[g][1], acc[g][2], acc[g][3],
                            a00, a01, a02, a03, bf[g].z, bf[g].w);
                    mma_acc(acc[g][4], acc[g][5], acc[g][6], acc[g][7],
                            a10, a11, a12, a13, bf[g].z, bf[g].w);
                }
            }
        }

        // write split-K partials: token cols g*8+2c, 2c+1 ; rows r0, +8, +16, +24
        float* base = g_part + (size_t)blockIdx.y * (TOKENS * NFEAT);
        #pragma unroll
        for (int g = 0; g < 4; ++g){
            const int t0c = g * 8 + 2 * c;
            base[(size_t)t0c       * NFEAT + r0     ] = acc[g][0];
            base[(size_t)(t0c + 1) * NFEAT + r0     ] = acc[g][1];
            base[(size_t)t0c       * NFEAT + r0 +  8] = acc[g][2];
            base[(size_t)(t0c + 1) * NFEAT + r0 +  8] = acc[g][3];
            base[(size_t)t0c       * NFEAT + r0 + 16] = acc[g][4];
            base[(size_t)(t0c + 1) * NFEAT + r0 + 16] = acc[g][5];
            base[(size_t)t0c       * NFEAT + r0 + 24] = acc[g][6];
            base[(size_t)(t0c + 1) * NFEAT + r0 + 24] = acc[g][7];
        }
    }
    grid_barrier(1);

    // ========== phase 2: split-K reduce + bias (one float4 per thread) ==========
    {
        const int i4 = t;                           // 0..65535 covers 32*8192/4
        const float4 b = *reinterpret_cast<const float4*>(bias + ((i4 * 4) & (NFEAT - 1)));
        float4 s = b;
        #pragma unroll
        for (int cp = 0; cp < KSPLIT; ++cp){
            const float4 v = *reinterpret_cast<const float4*>(
                g_part + (size_t)cp * (TOKENS * NFEAT) + (size_t)i4 * 4);
            s.x += v.x; s.y += v.y; s.z += v.z; s.w += v.w;
        }
        reinterpret_cast<float4*>(out)[i4] = s;
    }
}

extern "C" void kernel_launch(void* const* d_in, const int* in_sizes, int n_in,
                              void* d_out, int out_size)
{
    const float* inp    = (const float*)d_in[0];
    const int*   qw     = (const int*)  d_in[1];
    const float* scales = (const float*)d_in[2];
    const float* amax   = (const float*)d_in[3];
    const float* bias   = (const float*)d_in[4];
    float* out = (float*)d_out;

    dim3 grid(NFEAT / 128, KSPLIT);
    fp4_fused_kernel<<<grid, 128>>>(qw, scales, inp, amax, bias, out);
}